// round 16
// baseline (speedup 1.0000x reference)
#include <cuda_runtime.h>

#define BATCH    16
#define NTUP     65536
#define IN_SIZE  4096
#define OUT_SIZE 4096
#define TPB      512
#define CPB      37                      // CTAs per batch
#define GRID_MAIN (BATCH * CPB)          // 592 = one fully-resident wave
#define NCHUNK   256                     // chunks per batch (256 tuples each)
#define R0_CHUNKS 6                      // rank-0 CTA gets 6 (avg is 6.92)

__device__ int g_flag[BATCH];            // zero-init; reset each launch
__device__ int g_done;                   // zero-init; reset each launch

__global__ __launch_bounds__(TPB, 4)
void hyper_main_kernel(const float*  __restrict__ x,
                       const float2* __restrict__ means,
                       const float*  __restrict__ sigmas,
                       const float*  __restrict__ values,
                       const float4* __restrict__ noise,
                       const float*  __restrict__ bias,
                       float* __restrict__ y) {
    __shared__ float sx[IN_SIZE];
    __shared__ float sy[OUT_SIZE];   // per-CTA private accumulator

    const int b = blockIdx.x & 15;   // batch
    const int r = blockIdx.x >> 4;   // rank within batch (0..36)

    // stage x[b] into shared + zero the private accumulator
    {
        const float4* xb4 = reinterpret_cast<const float4*>(x + b * IN_SIZE);
        float4* sx4 = reinterpret_cast<float4*>(sx);
        float4* sy4 = reinterpret_cast<float4*>(sy);
        const float4 z = make_float4(0.f, 0.f, 0.f, 0.f);
        #pragma unroll
        for (int i = threadIdx.x; i < IN_SIZE / 4; i += TPB) {
            sx4[i] = xb4[i];
            sy4[i] = z;
        }
    }
    __syncthreads();

    // two adjacent lanes share one tuple; each lane owns 4 of the 8 samples
    const int h   = threadIdx.x & 1;             // half selector
    const int bn0 = b * NTUP;

    // chunked assignment: chunk = 256 tuples (one iteration of all pairs).
    // rank0: chunks [0, R0_CHUNKS) -> finishes early, flushes first.
    // ranks 1..36: chunks R0_CHUNKS + (r-1) + 36*i  (exact partition of 256)
    const int c0   = (r == 0) ? 0 : R0_CHUNKS + (r - 1);
    const int cs   = (r == 0) ? 1 : (CPB - 1);
    const int cend = (r == 0) ? R0_CHUNKS : NCHUNK;

    for (int c = c0; c < cend; c += cs) {
        const int t  = c * (TPB / 2) + (threadIdx.x >> 1);
        const int bn = bn0 + t;

        const float2 mu  = means[bn];    // pair-duplicated, sector-shared
        const float  sg  = sigmas[bn];
        const float  val = values[bn];

        // this lane's 8 noise floats (consecutive tids -> contiguous float4s)
        const float4 nza = noise[bn * 4 + 2 * h + 0];
        const float4 nzb = noise[bn * 4 + 2 * h + 1];
        const float nr[8] = { nza.x, nza.y, nza.z, nza.w,
                              nzb.x, nzb.y, nzb.z, nzb.w };

        // probs: sigma and the 2*pi*s2 denominator cancel in the
        // D-normalization, so probs depend only on the noise.
        float p[4];
        float psum = 0.0f;
        #pragma unroll
        for (int d = 0; d < 4; d++) {
            const float a = nr[2 * d + 0];
            const float c2 = nr[2 * d + 1];
            p[d] = __expf(-0.5f * (a * a + c2 * c2));
            psum += p[d];
        }
        // combine the two half-sums across the lane pair
        psum += __shfl_xor_sync(0xffffffffu, psum, 1);
        const float scale = __fdividef(val, psum);

        // 4 samples: address math + gather
        int   oi[4];
        float contrib[4];
        #pragma unroll
        for (int d = 0; d < 4; d++) {
            const float s0 = fmaf(nr[2 * d + 0], sg, mu.x);
            const float s1 = fmaf(nr[2 * d + 1], sg, mu.y);
            float f0 = rintf(s0);   // round-half-even == jnp.round
            float f1 = rintf(s1);
            f0 = fminf(fmaxf(f0, 0.0f), (float)(OUT_SIZE - 1));
            f1 = fminf(fmaxf(f1, 0.0f), (float)(IN_SIZE - 1));
            oi[d] = (int)f0;
            contrib[d] = (scale * p[d]) * sx[(int)f1];
        }

        // merge samples sharing an output row (within this lane's half)
        #pragma unroll
        for (int d = 1; d < 4; d++) {
            const float cd = contrib[d];
            bool merged = false;
            #pragma unroll
            for (int j = 0; j < d; j++) {
                const bool eq = (!merged) && (oi[d] == oi[j]);
                if (eq) contrib[j] += cd;
                merged = merged || eq;
            }
            if (merged) oi[d] = -1;
        }

        #pragma unroll
        for (int d = 0; d < 4; d++) {
            if (oi[d] >= 0)
                atomicAdd(&sy[oi[d]], contrib[d]);
        }
    }

    __syncthreads();

    const float4* sy4 = reinterpret_cast<const float4*>(sy);
    float4* yb4 = reinterpret_cast<float4*>(y + b * OUT_SIZE);

    if (r == 0) {
        // initializer CTA: plain store of bias + partial (overwrites poison)
        const float4* bias4 = reinterpret_cast<const float4*>(bias);
        #pragma unroll
        for (int i = threadIdx.x; i < OUT_SIZE / 4; i += TPB) {
            const float4 v = sy4[i];
            const float4 bv = bias4[i];
            yb4[i] = make_float4(v.x + bv.x, v.y + bv.y,
                                 v.z + bv.z, v.w + bv.w);
        }
        __threadfence();            // release: stores visible before flag
        __syncthreads();
        if (threadIdx.x == 0)
            atomicExch(&g_flag[b], 1);

        // CTA 0 restores device state for the next graph replay
        if (blockIdx.x == 0 && threadIdx.x == 0) {
            while (atomicAdd(&g_done, 0) < (GRID_MAIN - BATCH))
                __nanosleep(200);
            atomicExch(&g_done, 0);
            #pragma unroll
            for (int i = 0; i < BATCH; i++)
                atomicExch(&g_flag[i], 0);
            __threadfence();
        }
    } else {
        // wait for this batch's initializer, then accumulate with RED
        if (threadIdx.x == 0) {
            while (atomicAdd(&g_flag[b], 0) == 0)
                __nanosleep(100);
        }
        __syncthreads();
        __threadfence();            // acquire: order REDs after the STGs
        #pragma unroll
        for (int i = threadIdx.x; i < OUT_SIZE / 4; i += TPB) {
            const float4 v = sy4[i];
            asm volatile("red.global.add.v4.f32 [%0], {%1, %2, %3, %4};"
                         :: "l"(yb4 + i), "f"(v.x), "f"(v.y), "f"(v.z), "f"(v.w)
                         : "memory");
        }
        __syncthreads();
        if (threadIdx.x == 0)
            atomicAdd(&g_done, 1);
    }
}

extern "C" void kernel_launch(void* const* d_in, const int* in_sizes, int n_in,
                              void* d_out, int out_size) {
    const float*  x      = (const float*) d_in[0];  // [16, 4096]
    const float2* means  = (const float2*)d_in[1];  // [16, 65536, 2]
    const float*  sigmas = (const float*) d_in[2];  // [16, 65536]
    const float*  values = (const float*) d_in[3];  // [16, 65536]
    const float*  bias   = (const float*) d_in[4];  // [4096]
    const float4* noise  = (const float4*)d_in[5];  // [16, 65536, 8, 2]
    float* y = (float*)d_out;                       // [16, 4096]

    // single launch: rank-0 CTAs initialize y (bias + own partial) and
    // publish; the rest RED their partials after the handshake.
    hyper_main_kernel<<<GRID_MAIN, TPB>>>(x, means, sigmas, values, noise,
                                          bias, y);
}

// round 17
// speedup vs baseline: 1.0496x; 1.0496x over previous
#include <cuda_runtime.h>

#define BATCH    16
#define NTUP     65536
#define IN_SIZE  4096
#define OUT_SIZE 4096
#define TPB      512
#define CPB      37                      // CTAs per batch
#define GRID_MAIN (BATCH * CPB)          // 592 = one fully-resident wave
#define NCHUNK   256                     // chunks per batch (256 tuples each)
#define R0_CHUNKS 6                      // rank-0 CTA gets 6 (avg is 6.92)

// Monotonic per-batch epoch counters. NEVER reset: spinners compare against
// a snapshot taken at kernel start, so absolute values are irrelevant and
// the kernel stays deterministic across graph replays.
__device__ int g_flag[BATCH];

__global__ __launch_bounds__(TPB, 4)
void hyper_main_kernel(const float*  __restrict__ x,
                       const float2* __restrict__ means,
                       const float*  __restrict__ sigmas,
                       const float*  __restrict__ values,
                       const float4* __restrict__ noise,
                       const float*  __restrict__ bias,
                       float* __restrict__ y) {
    __shared__ float sx[IN_SIZE];
    __shared__ float sy[OUT_SIZE];   // per-CTA private accumulator
    __shared__ int   s_base;         // epoch snapshot (spinner CTAs)

    const int b = blockIdx.x & 15;   // batch
    const int r = blockIdx.x >> 4;   // rank within batch (0..36)

    // snapshot the epoch BEFORE any heavy work (all CTAs of the single wave
    // are co-resident from launch; rank-0 publishes ~15us later)
    if (r != 0 && threadIdx.x == 0)
        s_base = atomicAdd(&g_flag[b], 0);

    // stage x[b] into shared + zero the private accumulator
    {
        const float4* xb4 = reinterpret_cast<const float4*>(x + b * IN_SIZE);
        float4* sx4 = reinterpret_cast<float4*>(sx);
        float4* sy4 = reinterpret_cast<float4*>(sy);
        const float4 z = make_float4(0.f, 0.f, 0.f, 0.f);
        #pragma unroll
        for (int i = threadIdx.x; i < IN_SIZE / 4; i += TPB) {
            sx4[i] = xb4[i];
            sy4[i] = z;
        }
    }
    __syncthreads();

    // two adjacent lanes share one tuple; each lane owns 4 of the 8 samples
    const int h   = threadIdx.x & 1;             // half selector
    const int bn0 = b * NTUP;

    // chunk = 256 consecutive tuples. rank0: chunks [0, R0_CHUNKS) ->
    // finishes early, initializes y first. ranks 1..36: the remaining 250
    // chunks, strided (exact partition of 256).
    const int c0   = (r == 0) ? 0 : R0_CHUNKS + (r - 1);
    const int cs   = (r == 0) ? 1 : (CPB - 1);
    const int cend = (r == 0) ? R0_CHUNKS : NCHUNK;

    for (int c = c0; c < cend; c += cs) {
        const int t  = c * (TPB / 2) + (threadIdx.x >> 1);
        const int bn = bn0 + t;

        const float2 mu  = means[bn];    // pair-duplicated, sector-shared
        const float  sg  = sigmas[bn];
        const float  val = values[bn];

        // this lane's 8 noise floats (consecutive tids -> contiguous float4s)
        const float4 nza = noise[bn * 4 + 2 * h + 0];
        const float4 nzb = noise[bn * 4 + 2 * h + 1];
        const float nr[8] = { nza.x, nza.y, nza.z, nza.w,
                              nzb.x, nzb.y, nzb.z, nzb.w };

        // probs: sigma and the 2*pi*s2 denominator cancel in the
        // D-normalization, so probs depend only on the noise.
        float p[4];
        float psum = 0.0f;
        #pragma unroll
        for (int d = 0; d < 4; d++) {
            const float a  = nr[2 * d + 0];
            const float c2 = nr[2 * d + 1];
            p[d] = __expf(-0.5f * (a * a + c2 * c2));
            psum += p[d];
        }
        // combine the two half-sums across the lane pair
        psum += __shfl_xor_sync(0xffffffffu, psum, 1);
        const float scale = __fdividef(val, psum);

        // 4 samples: address math + gather
        int   oi[4];
        float contrib[4];
        #pragma unroll
        for (int d = 0; d < 4; d++) {
            const float s0 = fmaf(nr[2 * d + 0], sg, mu.x);
            const float s1 = fmaf(nr[2 * d + 1], sg, mu.y);
            float f0 = rintf(s0);   // round-half-even == jnp.round
            float f1 = rintf(s1);
            f0 = fminf(fmaxf(f0, 0.0f), (float)(OUT_SIZE - 1));
            f1 = fminf(fmaxf(f1, 0.0f), (float)(IN_SIZE - 1));
            oi[d] = (int)f0;
            contrib[d] = (scale * p[d]) * sx[(int)f1];
        }

        // merge samples sharing an output row (within this lane's half)
        #pragma unroll
        for (int d = 1; d < 4; d++) {
            const float cd = contrib[d];
            bool merged = false;
            #pragma unroll
            for (int j = 0; j < d; j++) {
                const bool eq = (!merged) && (oi[d] == oi[j]);
                if (eq) contrib[j] += cd;
                merged = merged || eq;
            }
            if (merged) oi[d] = -1;
        }

        #pragma unroll
        for (int d = 0; d < 4; d++) {
            if (oi[d] >= 0)
                atomicAdd(&sy[oi[d]], contrib[d]);
        }
    }

    __syncthreads();

    const float4* sy4 = reinterpret_cast<const float4*>(sy);
    float4* yb4 = reinterpret_cast<float4*>(y + b * OUT_SIZE);

    if (r == 0) {
        // initializer CTA: plain store of bias + own partial (over poison)
        const float4* bias4 = reinterpret_cast<const float4*>(bias);
        #pragma unroll
        for (int i = threadIdx.x; i < OUT_SIZE / 4; i += TPB) {
            const float4 v  = sy4[i];
            const float4 bv = bias4[i];
            yb4[i] = make_float4(v.x + bv.x, v.y + bv.y,
                                 v.z + bv.z, v.w + bv.w);
        }
        __threadfence();            // release: stores visible before publish
        __syncthreads();
        if (threadIdx.x == 0)
            atomicAdd(&g_flag[b], 1);   // publish epoch b
        // CTA retires immediately: no reset, no global tail.
    } else {
        // wait for this batch's initializer, then accumulate with RED
        if (threadIdx.x == 0) {
            const int base = s_base;
            while (atomicAdd(&g_flag[b], 0) == base)
                __nanosleep(100);
        }
        __syncthreads();
        __threadfence();            // acquire: order REDs after the STGs
        #pragma unroll
        for (int i = threadIdx.x; i < OUT_SIZE / 4; i += TPB) {
            const float4 v = sy4[i];
            asm volatile("red.global.add.v4.f32 [%0], {%1, %2, %3, %4};"
                         :: "l"(yb4 + i), "f"(v.x), "f"(v.y), "f"(v.z), "f"(v.w)
                         : "memory");
        }
    }
}

extern "C" void kernel_launch(void* const* d_in, const int* in_sizes, int n_in,
                              void* d_out, int out_size) {
    const float*  x      = (const float*) d_in[0];  // [16, 4096]
    const float2* means  = (const float2*)d_in[1];  // [16, 65536, 2]
    const float*  sigmas = (const float*) d_in[2];  // [16, 65536]
    const float*  values = (const float*) d_in[3];  // [16, 65536]
    const float*  bias   = (const float*) d_in[4];  // [4096]
    const float4* noise  = (const float4*)d_in[5];  // [16, 65536, 8, 2]
    float* y = (float*)d_out;                       // [16, 4096]

    // single launch: rank-0 CTAs initialize y (bias + own partial) and
    // publish an epoch; the remaining CTAs RED their partials afterward.
    hyper_main_kernel<<<GRID_MAIN, TPB>>>(x, means, sigmas, values, noise,
                                          bias, y);
}